// round 17
// baseline (speedup 1.0000x reference)
#include <cuda_runtime.h>
#include <cstdint>

#define SA 20        // alphabet
#define HH 2
#define KK 2
#define NM 4         // H*K matrices
#define LL 512
#define BB 1024
#define NRATES 100000
#define NPOW 7       // slots 1..6 used
#define PPB 512      // positions per consumer block
#define NBLK (BB * LL * HH / PPB)   // 2048 consumer blocks

// persistent scratch (allocation-free rule: __device__ globals)
__device__ float g_Qpow[NM][NPOW][SA * SA];
__device__ int   g_flag;

__device__ __forceinline__ float softplusf(float x) {
    return fmaxf(x, 0.f) + log1pf(expf(-fabsf(x)));
}

__global__ void reset_kernel() { g_flag = 0; }

// ---------------- Fused kernel ----------------
// Blocks 0..NM-1 (producers): build Q + powers Q^2..Q^6 -> g_Qpow -> flag. (~2us)
// Blocks NM.. (consumers): ballot-scan own 512 positions (hides producer latency),
//                          poll flag, Taylor P build, coalesced streaming write.
__global__ __launch_bounds__(256, 8)
void fused_kernel(const float* __restrict__ exch, const float* __restrict__ equil,
                  const float* __restrict__ inputs, const int* __restrict__ ridx,
                  const float* __restrict__ tauk, float* __restrict__ out) {
    const int t = threadIdx.x;

    if (blockIdx.x < NM) {
        // ================= producer: Q powers =================
        __shared__ float Q[SA * SA];
        __shared__ float A[SA * SA];
        __shared__ float Bm[SA * SA];
        __shared__ float esh[SA], pvec[SA], rowv[SA];
        __shared__ float inv_mue;

        const int m = blockIdx.x;

        if (t < SA) {
            float mx = -1e30f;
            for (int s = 0; s < SA; s++) mx = fmaxf(mx, equil[m * SA + s]);
            esh[t] = expf(equil[m * SA + t] - mx);
        }
        __syncthreads();
        if (t < SA) {
            float sum = 0.f;
            for (int s = 0; s < SA; s++) sum += esh[s];
            pvec[t] = esh[t] / sum;
        }
        __syncthreads();

        // pre-diagonal Q = softplus(0.5(Kij+Kji)) * (i!=j) * p_j
        for (int e = t; e < SA * SA; e += 256) {
            int i = e / SA, j = e % SA;
            float kij = exch[m * SA * SA + i * SA + j];
            float kji = exch[m * SA * SA + j * SA + i];
            float r = (i == j) ? 0.f : softplusf(0.5f * (kij + kji));
            Q[e] = r * pvec[j];
        }
        __syncthreads();
        if (t < SA) { float s = 0.f; for (int j = 0; j < SA; j++) s += Q[t * SA + j]; rowv[t] = s; }
        __syncthreads();
        if (t == 0) {
            float mue = 0.f;
            for (int i = 0; i < SA; i++) mue += pvec[i] * rowv[i];
            inv_mue = 1.f / fmaxf(mue, 1e-16f);
        }
        __syncthreads();
        for (int e = t; e < SA * SA; e += 256) {
            int i = e / SA, j = e % SA;
            Q[e] = (Q[e] - ((i == j) ? rowv[i] : 0.f)) * inv_mue;
        }
        __syncthreads();
        for (int e = t; e < SA * SA; e += 256) {
            g_Qpow[m][1][e] = Q[e];
            A[e] = Q[e];
        }
        __syncthreads();
        for (int n = 2; n <= 6; n++) {
            for (int e = t; e < SA * SA; e += 256) {
                int i = e / SA, j = e % SA;
                float acc = 0.f;
#pragma unroll
                for (int s = 0; s < SA; s++) acc += A[i * SA + s] * Q[s * SA + j];
                Bm[e] = acc;
            }
            __syncthreads();
            for (int e = t; e < SA * SA; e += 256) {
                A[e] = Bm[e];
                g_Qpow[m][n][e] = Bm[e];
            }
            __syncthreads();
        }
        __threadfence();
        __syncthreads();
        if (t == 0) atomicAdd(&g_flag, 1);
        return;
    }

    // ================= consumer =================
    __shared__ __align__(16) float Pm[NM * SA * SA];   // [(h*KK+k)*400 + z*20 + s]
    __shared__ unsigned int masks[8][8];               // 5 masks + pad per warp
    __shared__ unsigned char zsh[PPB];
    __shared__ float tau[HH];

    const int blk = blockIdx.x - NM;
    const int b = blk >> 1;                 // 2 blocks per batch item
    const int w = t >> 5;
    const int lane = t & 31;
    const int posbase = blk * PPB;

    if (t < HH) {
        int idx = ridx[b * HH + t];
        tau[t] = softplusf(tauk[t * NRATES + idx]);
    }

    // ---- Phase A: ballot scan of own 512 positions (hides producer latency) ----
    const float* ibase = inputs + (size_t)posbase * SA;
#pragma unroll
    for (int r = 0; r < 8; r++) {
        int relpos = (r * 8 + w) * 8;           // first of 8 positions this warp/round
        const float* ep = ibase + relpos * SA;  // 160 consecutive elements
#pragma unroll
        for (int k = 0; k < 5; k++) {
            float v = __ldcs(ep + k * 32 + lane);
            unsigned int mk = __ballot_sync(0xffffffffu, v > 0.5f);
            if (lane == k) masks[w][k] = mk;
        }
        if (lane == 5) masks[w][5] = 0u;        // pad for word+1
        __syncwarp();
        if (lane < 8) {
            int bitpos = 20 * lane;
            int word = bitpos >> 5;
            int sh = bitpos & 31;
            unsigned int bits = __funnelshift_r(masks[w][word], masks[w][word + 1], sh) & 0xFFFFFu;
            zsh[relpos + lane] = (unsigned char)(__ffs(bits) - 1);
        }
        __syncwarp();
    }

    // ---- wait for producers (usually already done) ----
    if (t == 0) {
        volatile int* vf = &g_flag;
        while (*vf < NM) { __nanosleep(64); }
    }
    __syncthreads();
    __threadfence();

    // ---- Phase B: P = I + tau(Q1 + tau/2(Q2 + ... + tau/6 Q6)) ----
    for (int e = t; e < NM * SA * SA; e += 256) {
        int m = e / (SA * SA);
        int rs = e - m * (SA * SA);
        int i = rs / SA, j = rs - i * SA;
        float th = tau[m >> 1];                 // m = h*KK + k
        const float* qp = &g_Qpow[m][0][rs];
        float q1 = qp[1 * SA * SA];
        float q2 = qp[2 * SA * SA];
        float q3 = qp[3 * SA * SA];
        float q4 = qp[4 * SA * SA];
        float q5 = qp[5 * SA * SA];
        float q6 = qp[6 * SA * SA];
        float v = q5 + (th * (1.f / 6.f)) * q6;
        v = q4 + (th * (1.f / 5.f)) * v;
        v = q3 + (th * (1.f / 4.f)) * v;
        v = q2 + (th * (1.f / 3.f)) * v;
        v = q1 + (th * (1.f / 2.f)) * v;
        Pm[e] = ((i == j) ? 1.f : 0.f) + th * v;
    }
    __syncthreads();

    // ---- Phase C: coalesced streaming write (PPB*40 floats = 5120 float4s) ----
    float4* op = (float4*)(out + (size_t)posbase * (KK * SA));
    int gp = t / 10;            // position-local of float4 index g = t
    int ge = t - 10 * gp;       // element 0..9 within position
    for (int it = 0; it < 20; it++) {
        int z = zsh[gp];
        int h = gp & 1;                        // posbase multiple of 512 -> parity kept
        int k = (ge >= 5) ? 1 : 0;
        int off = (h * KK + k) * (SA * SA) + z * SA + (ge - 5 * k) * 4;
        float4 v = *(const float4*)&Pm[off];
        __stcs(op + t + it * 256, v);
        // advance g by 256 = 25*10 + 6
        gp += 25; ge += 6; if (ge >= 10) { ge -= 10; gp += 1; }
    }
}

extern "C" void kernel_launch(void* const* d_in, const int* in_sizes, int n_in,
                              void* d_out, int out_size) {
    const float* inputs = (const float*)d_in[0];   // (B,L,H,20) f32
    const int*   ridx   = (const int*)d_in[1];     // (B,H) i32
    const float* tauk   = (const float*)d_in[2];   // (H,NUM_RATES) f32
    const float* exch   = (const float*)d_in[3];   // (H,K,20,20) f32
    const float* equil  = (const float*)d_in[4];   // (H,K,20) f32
    float* out = (float*)d_out;                    // (B,L,H,K,20) f32

    reset_kernel<<<1, 1>>>();
    fused_kernel<<<NM + NBLK, 256>>>(exch, equil, inputs, ridx, tauk, out);
}